// round 14
// baseline (speedup 1.0000x reference)
#include <cuda_runtime.h>
#include <stdint.h>

// Problem constants (fixed by the dataset instance)
#define BB   8
#define QQ   32768
#define TT   64
#define MT   4
#define NCH  32            // query chunks per batch
#define QC   (QQ / NCH)    // 1024 queries per chunk
#define NTASK (TT * 2)     // 128 (target, source) tasks per batch

// Scratch: partial top-4 keys per (batch, chunk, task, m). 8*32*128*4*8B = 1 MB.
__device__ unsigned long long g_part[BB * NCH * NTASK * MT];

static __device__ __forceinline__ unsigned long long pack_key(float c, int idx) {
    return ((unsigned long long)__float_as_uint(c) << 32) | (unsigned int)idx;
}

// ---------------------------------------------------------------------------
// Phase 1: per (batch, chunk) block, 128 threads = 128 (src, target) tasks.
// Each thread scans QC queries from shared memory maintaining a sorted top-4.
// ---------------------------------------------------------------------------
__global__ void __launch_bounds__(128) phase1_kernel(
    const float4* __restrict__ pred,   // [B*Q] xyxy
    const float4* __restrict__ anch,   // [B*Q] xyxy
    const float4* __restrict__ gt)     // [B*T] xyxy
{
    __shared__ float4 sq[2][QC];       // cxcywh, [src][query]  (32 KB)

    const int ch  = blockIdx.x;
    const int b   = blockIdx.y;
    const int tid = threadIdx.x;

    // Load + convert query boxes for this chunk (both sources).
    const float4* pbase = pred + (size_t)b * QQ + (size_t)ch * QC;
    const float4* abase = anch + (size_t)b * QQ + (size_t)ch * QC;
    for (int i = tid; i < QC; i += 128) {
        float4 p = pbase[i];
        sq[0][i] = make_float4((p.x + p.z) * 0.5f, (p.y + p.w) * 0.5f,
                               p.z - p.x, p.w - p.y);
        float4 a = abase[i];
        sq[1][i] = make_float4((a.x + a.z) * 0.5f, (a.y + a.w) * 0.5f,
                               a.z - a.x, a.w - a.y);
    }
    __syncthreads();

    const int t = tid & 63;    // target
    const int s = tid >> 6;    // 0 = pred, 1 = anchor

    float4 g = gt[b * TT + t];
    const float gcx = (g.x + g.z) * 0.5f;
    const float gcy = (g.y + g.w) * 0.5f;
    const float gw  = g.z - g.x;
    const float gh  = g.w - g.y;

    const float4* qs = sq[s];
    const int base = ch * QC;

    float c0 = 3.0e38f, c1 = 3.0e38f, c2 = 3.0e38f, c3 = 3.0e38f;
    int   i0 = 0, i1 = 0, i2 = 0, i3 = 0;

    #pragma unroll 4
    for (int q = 0; q < QC; q++) {
        float4 Qv = qs[q];
        // Sum order matches XLA's sequential 4-wide reduce: ((d0+d1)+d2)+d3
        float c = fabsf(Qv.x - gcx);
        c += fabsf(Qv.y - gcy);
        c += fabsf(Qv.z - gw);
        c += fabsf(Qv.w - gh);
        if (c < c3) {
            // strict < keeps earlier (lower) indices first on exact ties,
            // matching top_k's stable ascending-index tie-break.
            c3 = c; i3 = base + q;
            if (c3 < c2) {
                float tc = c2; c2 = c3; c3 = tc;
                int   ti = i2; i2 = i3; i3 = ti;
                if (c2 < c1) {
                    tc = c1; c1 = c2; c2 = tc;
                    ti = i1; i1 = i2; i2 = ti;
                    if (c1 < c0) {
                        tc = c0; c0 = c1; c1 = tc;
                        ti = i0; i0 = i1; i1 = ti;
                    }
                }
            }
        }
    }

    unsigned long long* out =
        g_part + ((size_t)(b * NCH + ch) * NTASK + tid) * MT;  // task id == tid (s*64+t)
    out[0] = pack_key(c0, i0);
    out[1] = pack_key(c1, i1);
    out[2] = pack_key(c2, i2);
    out[3] = pack_key(c3, i3);
}

// ---------------------------------------------------------------------------
// Phase 2: merge 32 chunk-partials per task (packed-key total order), write
// idx_i into d_out[0 : half) and idx_j (= m % 4 pattern) into d_out[half : ),
// as FLOAT32 values. (Integer bit-pattern writes read back as float denormals
// ~= 0 explain the persistent exact-1.0 rel_err in prior rounds; harness
// output buffers use the float32 dtype vocabulary.)
// ---------------------------------------------------------------------------
__global__ void __launch_bounds__(128) phase2_kernel(float* __restrict__ out, int half)
{
    const int b   = blockIdx.x;
    const int tid = threadIdx.x;     // task id: s*64 + t
    const int s   = tid >> 6;
    const int t   = tid & 63;

    unsigned long long k0 = ~0ull, k1 = ~0ull, k2 = ~0ull, k3 = ~0ull;

    for (int ch = 0; ch < NCH; ch++) {
        const unsigned long long* p =
            g_part + ((size_t)(b * NCH + ch) * NTASK + tid) * MT;
        #pragma unroll
        for (int m = 0; m < MT; m++) {
            unsigned long long key = p[m];
            if (key < k3) {
                k3 = key;
                if (k3 < k2) {
                    unsigned long long tk = k2; k2 = k3; k3 = tk;
                    if (k2 < k1) {
                        tk = k1; k1 = k2; k2 = tk;
                        if (k1 < k0) { tk = k0; k0 = k1; k1 = tk; }
                    }
                }
            }
        }
    }

    // Output layout: idx_i[b][t*8 + s*4 + m]  (float32 elements)
    const int obase = b * (TT * 2 * MT) + t * (2 * MT) + s * MT;
    out[obase + 0] = (float)(int)(unsigned int)k0;
    out[obase + 1] = (float)(int)(unsigned int)k1;
    out[obase + 2] = (float)(int)(unsigned int)k2;
    out[obase + 3] = (float)(int)(unsigned int)k3;

    // idx_j second half: value = position % 4
    float* oj = out + half + obase;
    oj[0] = 0.0f; oj[1] = 1.0f; oj[2] = 2.0f; oj[3] = 3.0f;
}

extern "C" void kernel_launch(void* const* d_in, const int* in_sizes, int n_in,
                              void* d_out, int out_size)
{
    // Robust input identification via in_sizes (gt_boxes is uniquely small:
    // 8*64*4 = 2048 elements; the other two are 8*32768*4 = 1048576).
    //   alphabetical : {anchors, gt_boxes, pred_boxes} -> gt at slot 1
    //   insertion    : {pred_boxes, anchors, gt_boxes} -> gt at slot 2
    const float4 *pred, *anch, *gt;
    if (n_in >= 3 && in_sizes[1] < in_sizes[0] && in_sizes[1] < in_sizes[2]) {
        // alphabetical: anchors, gt_boxes, pred_boxes
        anch = (const float4*)d_in[0];
        gt   = (const float4*)d_in[1];
        pred = (const float4*)d_in[2];
    } else if (n_in >= 3 && in_sizes[2] < in_sizes[0] && in_sizes[2] < in_sizes[1]) {
        // insertion order: pred, anchors, gt
        pred = (const float4*)d_in[0];
        anch = (const float4*)d_in[1];
        gt   = (const float4*)d_in[2];
    } else {
        // gt first (unlikely): gt, then anchors, pred
        gt   = (const float4*)d_in[0];
        anch = (const float4*)d_in[1];
        pred = (const float4*)d_in[2];
    }

    phase1_kernel<<<dim3(NCH, BB), 128>>>(pred, anch, gt);
    phase2_kernel<<<BB, 128>>>((float*)d_out, out_size / 2);
}

// round 16
// speedup vs baseline: 1.5765x; 1.5765x over previous
#include <cuda_runtime.h>
#include <stdint.h>

// Problem constants (fixed by the dataset instance)
#define BB   8
#define QQ   32768
#define TT   64
#define MT   4
#define NCH  128           // query chunks per batch (raised 32->128 for occupancy)
#define QC   (QQ / NCH)    // 256 queries per chunk
#define NTASK (TT * 2)     // 128 (target, source) tasks per batch

// Scratch: partial top-4 keys per (batch, chunk, task, m). 8*128*128*4*8B = 4 MB.
__device__ unsigned long long g_part[(size_t)BB * NCH * NTASK * MT];

static __device__ __forceinline__ unsigned long long pack_key(float c, int idx) {
    return ((unsigned long long)__float_as_uint(c) << 32) | (unsigned int)idx;
}

// ---------------------------------------------------------------------------
// Phase 1: per (batch, chunk) block, 128 threads = 128 (src, target) tasks.
// Each thread scans QC queries from shared memory maintaining a sorted top-4.
// 8 KB smem/block -> ~7 resident blocks/SM -> latency hidden.
// ---------------------------------------------------------------------------
__global__ void __launch_bounds__(128) phase1_kernel(
    const float4* __restrict__ pred,   // [B*Q] xyxy
    const float4* __restrict__ anch,   // [B*Q] xyxy
    const float4* __restrict__ gt)     // [B*T] xyxy
{
    __shared__ float4 sq[2][QC];       // cxcywh, [src][query]  (8 KB)

    const int ch  = blockIdx.x;
    const int b   = blockIdx.y;
    const int tid = threadIdx.x;

    // Load + convert query boxes for this chunk (both sources).
    const float4* pbase = pred + (size_t)b * QQ + (size_t)ch * QC;
    const float4* abase = anch + (size_t)b * QQ + (size_t)ch * QC;
    #pragma unroll
    for (int i = tid; i < QC; i += 128) {
        float4 p = pbase[i];
        sq[0][i] = make_float4((p.x + p.z) * 0.5f, (p.y + p.w) * 0.5f,
                               p.z - p.x, p.w - p.y);
        float4 a = abase[i];
        sq[1][i] = make_float4((a.x + a.z) * 0.5f, (a.y + a.w) * 0.5f,
                               a.z - a.x, a.w - a.y);
    }
    __syncthreads();

    const int t = tid & 63;    // target
    const int s = tid >> 6;    // 0 = pred, 1 = anchor

    float4 g = gt[b * TT + t];
    const float gcx = (g.x + g.z) * 0.5f;
    const float gcy = (g.y + g.w) * 0.5f;
    const float gw  = g.z - g.x;
    const float gh  = g.w - g.y;

    const float4* qs = sq[s];
    const int base = ch * QC;

    float c0 = 3.0e38f, c1 = 3.0e38f, c2 = 3.0e38f, c3 = 3.0e38f;
    int   i0 = 0, i1 = 0, i2 = 0, i3 = 0;

    #pragma unroll 4
    for (int q = 0; q < QC; q++) {
        float4 Qv = qs[q];
        // Sum order matches XLA's sequential 4-wide reduce: ((d0+d1)+d2)+d3
        float c = fabsf(Qv.x - gcx);
        c += fabsf(Qv.y - gcy);
        c += fabsf(Qv.z - gw);
        c += fabsf(Qv.w - gh);
        if (c < c3) {
            // strict < keeps earlier (lower) indices first on exact ties,
            // matching top_k's stable ascending-index tie-break.
            c3 = c; i3 = base + q;
            if (c3 < c2) {
                float tc = c2; c2 = c3; c3 = tc;
                int   ti = i2; i2 = i3; i3 = ti;
                if (c2 < c1) {
                    tc = c1; c1 = c2; c2 = tc;
                    ti = i1; i1 = i2; i2 = ti;
                    if (c1 < c0) {
                        tc = c0; c0 = c1; c1 = tc;
                        ti = i0; i0 = i1; i1 = ti;
                    }
                }
            }
        }
    }

    unsigned long long* out =
        g_part + ((size_t)(b * NCH + ch) * NTASK + tid) * MT;  // task id == tid (s*64+t)
    out[0] = pack_key(c0, i0);
    out[1] = pack_key(c1, i1);
    out[2] = pack_key(c2, i2);
    out[3] = pack_key(c3, i3);
}

// ---------------------------------------------------------------------------
// Phase 2: one warp per task. Lane l merges chunks {l, l+32, l+64, l+96}
// sequentially (sorted inputs), then 4 rounds of warp-wide min-extraction
// produce the global sorted top-4. Keys are unique (low bits = query index),
// so exactly one lane pops per round.
// Output float32: idx_i in [0, half), idx_j (= m % 4) in [half, 2*half).
// ---------------------------------------------------------------------------
__global__ void __launch_bounds__(256) phase2_kernel(float* __restrict__ out, int half)
{
    const int warp = threadIdx.x >> 5;
    const int lane = threadIdx.x & 31;
    const int task = blockIdx.x * 8 + warp;   // 0 .. BB*NTASK-1
    const int b      = task >> 7;
    const int tid128 = task & 127;            // s*64 + t
    const int s      = tid128 >> 6;
    const int t      = tid128 & 63;

    unsigned long long k0 = ~0ull, k1 = ~0ull, k2 = ~0ull, k3 = ~0ull;

    #pragma unroll
    for (int j = 0; j < NCH / 32; j++) {
        const int ch = lane + 32 * j;
        const unsigned long long* p =
            g_part + ((size_t)(b * NCH + ch) * NTASK + tid128) * MT;
        #pragma unroll
        for (int m = 0; m < MT; m++) {
            unsigned long long key = p[m];
            if (key < k3) {
                k3 = key;
                if (k3 < k2) {
                    unsigned long long tk = k2; k2 = k3; k3 = tk;
                    if (k2 < k1) {
                        tk = k1; k1 = k2; k2 = tk;
                        if (k1 < k0) { tk = k0; k0 = k1; k1 = tk; }
                    }
                }
            }
        }
    }

    // 4 rounds of warp min-extraction (keys unique -> one popper per round).
    unsigned long long res0, res1, res2, res3;
    #pragma unroll
    for (int r = 0; r < 4; r++) {
        unsigned long long m = k0;
        #pragma unroll
        for (int off = 16; off; off >>= 1) {
            unsigned long long o = __shfl_xor_sync(0xffffffffu, m, off);
            if (o < m) m = o;
        }
        if (k0 == m) { k0 = k1; k1 = k2; k2 = k3; k3 = ~0ull; }
        if (r == 0) res0 = m; else if (r == 1) res1 = m;
        else if (r == 2) res2 = m; else res3 = m;
    }

    if (lane == 0) {
        // Output layout: idx_i[b][t*8 + s*4 + m]  (float32 elements)
        const int obase = b * (TT * 2 * MT) + t * (2 * MT) + s * MT;
        out[obase + 0] = (float)(unsigned int)res0;
        out[obase + 1] = (float)(unsigned int)res1;
        out[obase + 2] = (float)(unsigned int)res2;
        out[obase + 3] = (float)(unsigned int)res3;

        float* oj = out + half + obase;
        oj[0] = 0.0f; oj[1] = 1.0f; oj[2] = 2.0f; oj[3] = 3.0f;
    }
}

extern "C" void kernel_launch(void* const* d_in, const int* in_sizes, int n_in,
                              void* d_out, int out_size)
{
    // Robust input identification via in_sizes (gt_boxes is uniquely small:
    // 8*64*4 = 2048 elements; the other two are 8*32768*4 = 1048576).
    const float4 *pred, *anch, *gt;
    if (n_in >= 3 && in_sizes[1] < in_sizes[0] && in_sizes[1] < in_sizes[2]) {
        // alphabetical: anchors, gt_boxes, pred_boxes
        anch = (const float4*)d_in[0];
        gt   = (const float4*)d_in[1];
        pred = (const float4*)d_in[2];
    } else if (n_in >= 3 && in_sizes[2] < in_sizes[0] && in_sizes[2] < in_sizes[1]) {
        // insertion order: pred, anchors, gt
        pred = (const float4*)d_in[0];
        anch = (const float4*)d_in[1];
        gt   = (const float4*)d_in[2];
    } else {
        // gt first (unlikely): gt, then anchors, pred
        gt   = (const float4*)d_in[0];
        anch = (const float4*)d_in[1];
        pred = (const float4*)d_in[2];
    }

    phase1_kernel<<<dim3(NCH, BB), 128>>>(pred, anch, gt);
    phase2_kernel<<<(BB * NTASK) / 8, 256>>>((float*)d_out, out_size / 2);
}

// round 17
// speedup vs baseline: 2.1364x; 1.3551x over previous
#include <cuda_runtime.h>
#include <stdint.h>

// Problem constants (fixed by the dataset instance)
#define BB   8
#define QQ   32768
#define TT   64
#define MT   4
#define NCH  128           // query chunks per batch
#define QC   (QQ / NCH)    // 256 queries per chunk
#define NTASK (TT * 2)     // 128 (target, source) tasks per batch

// Scratch: partial top-4 keys per (batch, chunk, task, m). 8*128*128*4*8B = 4 MB.
__device__ unsigned long long g_part[(size_t)BB * NCH * NTASK * MT];

static __device__ __forceinline__ unsigned long long pack_key(float c, int idx) {
    return ((unsigned long long)__float_as_uint(c) << 32) | (unsigned int)idx;
}

// Flat predicated insert of (c, qi) into sorted (c0..c3, i0..i3).
// Strict < places new value AFTER all equal-valued entries -> identical to the
// stable sequential scan (top_k lower-index tie-break preserved).
#define FLAT_INSERT(c, qi)                                            \
    {                                                                 \
        bool p0 = (c) < c0, p1 = (c) < c1, p2 = (c) < c2, p3 = (c) < c3; \
        c3 = p3 ? (p2 ? c2 : (c)) : c3;  i3 = p3 ? (p2 ? i2 : (qi)) : i3; \
        c2 = p2 ? (p1 ? c1 : (c)) : c2;  i2 = p2 ? (p1 ? i1 : (qi)) : i2; \
        c1 = p1 ? (p0 ? c0 : (c)) : c1;  i1 = p1 ? (p0 ? i0 : (qi)) : i1; \
        c0 = p0 ? (c) : c0;              i0 = p0 ? (qi) : i0;             \
    }

// ---------------------------------------------------------------------------
// Phase 1: per (batch, chunk) block, 128 threads = 128 (src, target) tasks.
// Each thread scans QC queries (2 per iteration) from shared memory keeping a
// sorted top-4 via a single-branch flat predicated insert.
// ---------------------------------------------------------------------------
__global__ void __launch_bounds__(128) phase1_kernel(
    const float4* __restrict__ pred,   // [B*Q] xyxy
    const float4* __restrict__ anch,   // [B*Q] xyxy
    const float4* __restrict__ gt)     // [B*T] xyxy
{
    __shared__ float4 sq[2][QC];       // cxcywh, [src][query]  (8 KB)

    const int ch  = blockIdx.x;
    const int b   = blockIdx.y;
    const int tid = threadIdx.x;

    const float4* pbase = pred + (size_t)b * QQ + (size_t)ch * QC;
    const float4* abase = anch + (size_t)b * QQ + (size_t)ch * QC;
    #pragma unroll
    for (int i = tid; i < QC; i += 128) {
        float4 p = pbase[i];
        sq[0][i] = make_float4((p.x + p.z) * 0.5f, (p.y + p.w) * 0.5f,
                               p.z - p.x, p.w - p.y);
        float4 a = abase[i];
        sq[1][i] = make_float4((a.x + a.z) * 0.5f, (a.y + a.w) * 0.5f,
                               a.z - a.x, a.w - a.y);
    }
    __syncthreads();

    const int t = tid & 63;    // target
    const int s = tid >> 6;    // 0 = pred, 1 = anchor

    float4 g = gt[b * TT + t];
    const float gcx = (g.x + g.z) * 0.5f;
    const float gcy = (g.y + g.w) * 0.5f;
    const float gw  = g.z - g.x;
    const float gh  = g.w - g.y;

    const float4* qs = sq[s];
    const int base = ch * QC;

    float c0 = 3.0e38f, c1 = 3.0e38f, c2 = 3.0e38f, c3 = 3.0e38f;
    int   i0 = 0, i1 = 0, i2 = 0, i3 = 0;

    #pragma unroll 2
    for (int q = 0; q < QC; q += 2) {
        float4 A  = qs[q];
        float4 Bv = qs[q + 1];
        // Sum order matches XLA's sequential 4-wide reduce: ((d0+d1)+d2)+d3
        float ca = fabsf(A.x - gcx);
        ca += fabsf(A.y - gcy);
        ca += fabsf(A.z - gw);
        ca += fabsf(A.w - gh);
        float cb = fabsf(Bv.x - gcx);
        cb += fabsf(Bv.y - gcy);
        cb += fabsf(Bv.z - gw);
        cb += fabsf(Bv.w - gh);

        if (fminf(ca, cb) < c3) {
            // Insert in index order (a = q first, then b = q+1); each insert
            // is fully predicated, so non-qualifying values are no-ops.
            FLAT_INSERT(ca, base + q);
            FLAT_INSERT(cb, base + q + 1);
        }
    }

    unsigned long long* out =
        g_part + ((size_t)(b * NCH + ch) * NTASK + tid) * MT;  // task id == tid
    out[0] = pack_key(c0, i0);
    out[1] = pack_key(c1, i1);
    out[2] = pack_key(c2, i2);
    out[3] = pack_key(c3, i3);
}

// ---------------------------------------------------------------------------
// Phase 2: one warp per task. Lane l pre-loads chunks {l, l+32, l+64, l+96}
// (8 independent LDG.128 -> MLP hides DRAM/L2 latency), merges 16 keys into a
// lane-local sorted top-4, then 4 rounds of warp-wide min-extraction. Keys are
// unique (low bits = query index), so exactly one lane pops per round.
// Output float32: idx_i in [0, half), idx_j (= m % 4) in [half, 2*half).
// ---------------------------------------------------------------------------
__global__ void __launch_bounds__(256) phase2_kernel(float* __restrict__ out, int half)
{
    const int warp = threadIdx.x >> 5;
    const int lane = threadIdx.x & 31;
    const int task = blockIdx.x * 8 + warp;   // 0 .. BB*NTASK-1
    const int b      = task >> 7;
    const int tid128 = task & 127;            // s*64 + t
    const int s      = tid128 >> 6;
    const int t      = tid128 & 63;

    // Pre-load all 16 keys (4 chunks x 4 sorted keys) up front for MLP.
    ulonglong4 v[4];
    #pragma unroll
    for (int j = 0; j < NCH / 32; j++) {
        const int ch = lane + 32 * j;
        v[j] = *(const ulonglong4*)(
            g_part + ((size_t)(b * NCH + ch) * NTASK + tid128) * MT);
    }

    unsigned long long k0 = ~0ull, k1 = ~0ull, k2 = ~0ull, k3 = ~0ull;
    #pragma unroll
    for (int j = 0; j < NCH / 32; j++) {
        // Chunk keys are sorted ascending; if the smallest doesn't beat k3,
        // none do.
        if (v[j].x < k3) {
            unsigned long long key = v[j].x;
            { bool p0=key<k0, p1=key<k1, p2=key<k2;
              k3 = p2 ? k2 : key;
              k2 = p2 ? (p1 ? k1 : key) : k2;
              k1 = p1 ? (p0 ? k0 : key) : k1;
              k0 = p0 ? key : k0; }
            key = v[j].y;
            if (key < k3) {
                bool p0=key<k0, p1=key<k1, p2=key<k2;
                k3 = p2 ? k2 : key;
                k2 = p2 ? (p1 ? k1 : key) : k2;
                k1 = p1 ? (p0 ? k0 : key) : k1;
                k0 = p0 ? key : k0;
                key = v[j].z;
                if (key < k3) {
                    bool q0=key<k0, q1=key<k1, q2=key<k2;
                    k3 = q2 ? k2 : key;
                    k2 = q2 ? (q1 ? k1 : key) : k2;
                    k1 = q1 ? (q0 ? k0 : key) : k1;
                    k0 = q0 ? key : k0;
                    key = v[j].w;
                    if (key < k3) {
                        bool r0=key<k0, r1=key<k1, r2=key<k2;
                        k3 = r2 ? k2 : key;
                        k2 = r2 ? (r1 ? k1 : key) : k2;
                        k1 = r1 ? (r0 ? k0 : key) : k1;
                        k0 = r0 ? key : k0;
                    }
                }
            }
        }
    }

    // 4 rounds of warp min-extraction (keys unique -> one popper per round).
    unsigned long long res0, res1, res2, res3;
    #pragma unroll
    for (int r = 0; r < 4; r++) {
        unsigned long long m = k0;
        #pragma unroll
        for (int off = 16; off; off >>= 1) {
            unsigned long long o = __shfl_xor_sync(0xffffffffu, m, off);
            if (o < m) m = o;
        }
        if (k0 == m) { k0 = k1; k1 = k2; k2 = k3; k3 = ~0ull; }
        if (r == 0) res0 = m; else if (r == 1) res1 = m;
        else if (r == 2) res2 = m; else res3 = m;
    }

    if (lane == 0) {
        // Output layout: idx_i[b][t*8 + s*4 + m]  (float32 elements)
        const int obase = b * (TT * 2 * MT) + t * (2 * MT) + s * MT;
        out[obase + 0] = (float)(unsigned int)res0;
        out[obase + 1] = (float)(unsigned int)res1;
        out[obase + 2] = (float)(unsigned int)res2;
        out[obase + 3] = (float)(unsigned int)res3;

        float* oj = out + half + obase;
        oj[0] = 0.0f; oj[1] = 1.0f; oj[2] = 2.0f; oj[3] = 3.0f;
    }
}

extern "C" void kernel_launch(void* const* d_in, const int* in_sizes, int n_in,
                              void* d_out, int out_size)
{
    // Robust input identification via in_sizes (gt_boxes is uniquely small:
    // 8*64*4 = 2048 elements; the other two are 8*32768*4 = 1048576).
    const float4 *pred, *anch, *gt;
    if (n_in >= 3 && in_sizes[1] < in_sizes[0] && in_sizes[1] < in_sizes[2]) {
        // alphabetical: anchors, gt_boxes, pred_boxes
        anch = (const float4*)d_in[0];
        gt   = (const float4*)d_in[1];
        pred = (const float4*)d_in[2];
    } else if (n_in >= 3 && in_sizes[2] < in_sizes[0] && in_sizes[2] < in_sizes[1]) {
        // insertion order: pred, anchors, gt
        pred = (const float4*)d_in[0];
        anch = (const float4*)d_in[1];
        gt   = (const float4*)d_in[2];
    } else {
        // gt first (unlikely): gt, then anchors, pred
        gt   = (const float4*)d_in[0];
        anch = (const float4*)d_in[1];
        pred = (const float4*)d_in[2];
    }

    phase1_kernel<<<dim3(NCH, BB), 128>>>(pred, anch, gt);
    phase2_kernel<<<(BB * NTASK) / 8, 256>>>((float*)d_out, out_size / 2);
}